// round 16
// baseline (speedup 1.0000x reference)
#include <cuda_runtime.h>
#include <cuda_fp16.h>
#include <math.h>
#include <stdint.h>

// Problem constants
#define B_    4
#define S_    2048
#define D_    1024
#define H_    16
#define DEPTH 64
#define MTOK  (B_ * S_)   // 8192 token rows

// ---------------------------------------------------------------------------
// Scratch (device globals; no allocation allowed)
// ---------------------------------------------------------------------------
__device__ __half g_in[3][MTOK * D_];     // fp16 inputs (v,k,q order)
__device__ __half g_wt[4][D_ * D_];       // fp16 transposed weights [N,K]
__device__ __half g_q[MTOK * D_];         // projected, head-split [B,H,S,64]
__device__ __half g_k[MTOK * D_];
__device__ __half g_v[MTOK * D_];
__device__ __half g_attn[MTOK * D_];      // attention output [B,S,D]

// ---------------------------------------------------------------------------
// PTX helpers (sm_103 base target: mma.sync / ldmatrix / cp.async only)
// ---------------------------------------------------------------------------
__device__ __forceinline__ uint32_t smem_u32(const void* p) {
    uint32_t a;
    asm("{ .reg .u64 t; cvta.to.shared.u64 t, %1; cvt.u32.u64 %0, t; }"
        : "=r"(a) : "l"(p));
    return a;
}

#define CP_ASYNC16(dst_u32, src_ptr) \
    asm volatile("cp.async.cg.shared.global [%0], [%1], 16;" \
                 :: "r"(dst_u32), "l"(src_ptr) : "memory")
#define CP_COMMIT() asm volatile("cp.async.commit_group;" ::: "memory")
#define CP_WAIT(n)  asm volatile("cp.async.wait_group %0;" :: "n"(n) : "memory")

#define LDSM_X4(r0, r1, r2, r3, addr) \
    asm volatile("ldmatrix.sync.aligned.m8n8.x4.shared.b16 {%0,%1,%2,%3}, [%4];" \
                 : "=r"(r0), "=r"(r1), "=r"(r2), "=r"(r3) : "r"(addr))

#define LDSM_X4_T(r0, r1, r2, r3, addr) \
    asm volatile("ldmatrix.sync.aligned.m8n8.x4.trans.shared.b16 {%0,%1,%2,%3}, [%4];" \
                 : "=r"(r0), "=r"(r1), "=r"(r2), "=r"(r3) : "r"(addr))

#define MMA_F16(d, a, b) \
    asm volatile("mma.sync.aligned.m16n8k16.row.col.f32.f16.f16.f32 " \
                 "{%0,%1,%2,%3}, {%4,%5,%6,%7}, {%8,%9}, {%0,%1,%2,%3};" \
                 : "+f"((d)[0]), "+f"((d)[1]), "+f"((d)[2]), "+f"((d)[3]) \
                 : "r"((a)[0]), "r"((a)[1]), "r"((a)[2]), "r"((a)[3]), \
                   "r"((b)[0]), "r"((b)[1]))

__device__ __forceinline__ uint32_t pack_h2(float x, float y) {
    __half2 h = __floats2half2_rn(x, y);
    return *reinterpret_cast<uint32_t*>(&h);
}

// element-wise exp2 on a packed half2
__device__ __forceinline__ uint32_t ex2_h2(uint32_t h2) {
    uint32_t r;
    asm("ex2.approx.f16x2 %0, %1;" : "=r"(r) : "r"(h2));
    return r;
}

// ---------------------------------------------------------------------------
// Fused prep kernel: z = 0..2 -> fp32->fp16 input converts (v,k,q);
//                    z = 3    -> all four weight transposes (blocks 0..4095)
// ---------------------------------------------------------------------------
__global__ void __launch_bounds__(256)
prep_all(const float* __restrict__ v, const float* __restrict__ k,
         const float* __restrict__ q,
         const float* __restrict__ wq, const float* __restrict__ wk,
         const float* __restrict__ wv, const float* __restrict__ wo)
{
    const int z = blockIdx.z;
    if (z < 3) {
        const float* src = (z == 0) ? v : (z == 1) ? k : q;
        __half* dst = g_in[z];
        const int i = blockIdx.x * blockDim.x + threadIdx.x;
        float4 val = reinterpret_cast<const float4*>(src)[i];
        uint32_t* dp = reinterpret_cast<uint32_t*>(dst);
        dp[2 * i]     = pack_h2(val.x, val.y);
        dp[2 * i + 1] = pack_h2(val.z, val.w);
    } else {
        if (blockIdx.x >= 4096) return;
        __shared__ float t[32][33];
        const int w = blockIdx.x >> 10;             // weight index 0..3
        const int tile = blockIdx.x & 1023;
        const int nx = (tile & 31) * 32;            // N tile
        const int kx = (tile >> 5) * 32;            // K tile
        const float* W = (w == 0) ? wq : (w == 1) ? wk : (w == 2) ? wv : wo;
        __half* T = g_wt[w];
        const int tx = threadIdx.x & 31;
        const int ty = threadIdx.x >> 5;            // 0..7
        #pragma unroll
        for (int r = 0; r < 32; r += 8)
            t[ty + r][tx] = W[(size_t)(kx + ty + r) * D_ + nx + tx];
        __syncthreads();
        #pragma unroll
        for (int r = 0; r < 32; r += 8)
            T[(size_t)(nx + ty + r) * D_ + kx + tx] = __float2half_rn(t[tx][ty + r]);
    }
}

// ---------------------------------------------------------------------------
// fp16 HMMA GEMM body: CTA tile 128x128, 256 threads (8 warps, 2x4 grid of
// 64x32 warp tiles), K-block 64, 2-stage cp.async, 2 CTAs/SM (16 warps/SM).
// Combines low global traffic (A reloads = N/128 = 8) with high occupancy.
// Per-warp acc = 64 regs -> ~115 regs/thread, fits 2 x 256 threads.
// MODE 0: C fp32 row-major [M,N]
// MODE 1: C fp16 head-split [B,H,S,DEPTH]
// ---------------------------------------------------------------------------
#define LDT        72                        // smem row stride in fp16 (144B)
#define TILE_B     (128 * LDT * 2)           // 18432 bytes (128 rows x 64 halves)
#define STAGE_B    (2 * TILE_B)              // A + B = 36864
#define GEMM_SMEM  (2 * STAGE_B)             // 73728 -> 2 CTAs/SM

template <int MODE>
__device__ __forceinline__ void
gemm_body(const __half* __restrict__ A, const __half* __restrict__ Bm,
          const float* __restrict__ bias, float* __restrict__ C,
          __half* __restrict__ Ch, float alpha)
{
    extern __shared__ char smem[];
    const uint32_t sb = smem_u32(smem);

    const int tid  = threadIdx.x;        // 0..255
    const int wid  = tid >> 5;           // 0..7
    const int lane = tid & 31;
    const int wm   = wid & 1;            // warp row -> 64 M-rows
    const int wn   = wid >> 1;           // warp col (0..3) -> 32 N-cols
    const int m0   = blockIdx.y * 128;
    const int n0   = blockIdx.x * 128;

    const __half* srcs[2] = {A, Bm};
    const int rowbase[2] = {m0, n0};

    auto load_stage = [&](int kb, int buf) {
        const uint32_t st = sb + buf * STAGE_B;
        #pragma unroll
        for (int t = 0; t < 2; t++) {
            const __half* s = srcs[t];
            const int rb = rowbase[t];
            #pragma unroll
            for (int r = 0; r < 4; r++) {
                const int idx  = r * 256 + tid;
                const int row  = idx >> 3;
                const int ch   = idx & 7;
                CP_ASYNC16(st + t * TILE_B + row * (LDT * 2) + ch * 16,
                           s + (size_t)(rb + row) * D_ + kb * 64 + ch * 8);
            }
        }
        CP_COMMIT();
    };

    float acc[4][4][4];
    #pragma unroll
    for (int i = 0; i < 4; i++)
        #pragma unroll
        for (int j = 0; j < 4; j++)
            #pragma unroll
            for (int v = 0; v < 4; v++)
                acc[i][j][v] = 0.0f;

    load_stage(0, 0);
    load_stage(1, 1);

    const int a_r = lane & 15;
    const int a_c = (lane >> 4) << 3;
    const int b_r = (lane & 7) + ((lane >> 4) << 3);
    const int b_c = ((lane >> 3) & 1) << 3;

    const int NITER = D_ / 64;    // 16
    for (int kb = 0; kb < NITER; kb++) {
        if (kb == NITER - 1) { CP_WAIT(0); } else { CP_WAIT(1); }
        __syncthreads();

        const int buf = kb & 1;
        const uint32_t st = sb + buf * STAGE_B;
        const uint32_t tA = st;
        const uint32_t tB = st + TILE_B;

        #pragma unroll
        for (int ks = 0; ks < 64; ks += 16) {
            uint32_t ah[4][4];
            #pragma unroll
            for (int mf = 0; mf < 4; mf++) {
                const int row = wm * 64 + mf * 16 + a_r;
                const uint32_t off = row * (LDT * 2) + (ks + a_c) * 2;
                LDSM_X4(ah[mf][0], ah[mf][1], ah[mf][2], ah[mf][3], tA + off);
            }
            uint32_t bh[4][2];
            #pragma unroll
            for (int gp = 0; gp < 2; gp++) {
                const int row = wn * 32 + gp * 16 + b_r;
                const uint32_t off = row * (LDT * 2) + (ks + b_c) * 2;
                LDSM_X4(bh[2 * gp][0], bh[2 * gp][1], bh[2 * gp + 1][0], bh[2 * gp + 1][1],
                        tB + off);
            }
            #pragma unroll
            for (int mf = 0; mf < 4; mf++)
                #pragma unroll
                for (int nf = 0; nf < 4; nf++)
                    MMA_F16(acc[mf][nf], ah[mf], bh[nf]);
        }
        __syncthreads();
        if (kb + 2 < NITER) load_stage(kb + 2, buf);
    }

    const int er = lane >> 2;
    const int ec = (lane & 3) * 2;
    #pragma unroll
    for (int mf = 0; mf < 4; mf++) {
        #pragma unroll
        for (int nf = 0; nf < 4; nf++) {
            const int n  = n0 + wn * 32 + nf * 8 + ec;
            const float b0 = bias[n], b1 = bias[n + 1];
            #pragma unroll
            for (int half = 0; half < 2; half++) {
                const int m = m0 + wm * 64 + mf * 16 + er + half * 8;
                const float vx = (acc[mf][nf][half * 2 + 0] + b0) * alpha;
                const float vy = (acc[mf][nf][half * 2 + 1] + b1) * alpha;
                if (MODE == 0) {
                    float2 v; v.x = vx; v.y = vy;
                    *reinterpret_cast<float2*>(&C[(size_t)m * D_ + n]) = v;
                } else {
                    const int b  = m >> 11;
                    const int s  = m & 2047;
                    const int h  = n >> 6;
                    const int dd = n & 63;
                    const size_t idx = (((size_t)(b * H_ + h)) * S_ + s) * DEPTH + dd;
                    *reinterpret_cast<uint32_t*>(&Ch[idx]) = pack_h2(vx, vy);
                }
            }
        }
    }
}

// Q pre-scaled by (1/8)*log2(e) so softmax runs in exp2 domain.
#define QSCALE_LOG2E 0.1803368801111244f

__global__ void __launch_bounds__(256, 2)
qkv_gemm(const float* __restrict__ bq, const float* __restrict__ bk,
         const float* __restrict__ bv)
{
    const int z = blockIdx.z;
    if (z == 0) {
        gemm_body<1>(g_in[2], g_wt[0], bq, nullptr, g_q, QSCALE_LOG2E);
    } else if (z == 1) {
        gemm_body<1>(g_in[1], g_wt[1], bk, nullptr, g_k, 1.0f);
    } else {
        gemm_body<1>(g_in[0], g_wt[2], bv, nullptr, g_v, 1.0f);
    }
}

__global__ void __launch_bounds__(256, 2)
out_gemm(const float* __restrict__ bo, float* __restrict__ C)
{
    gemm_body<0>(g_attn, g_wt[3], bo, C, nullptr, 1.0f);
}

// ---------------------------------------------------------------------------
// Flash attention, fixed-scale exp2 softmax (unchanged from round 15).
// ---------------------------------------------------------------------------
#define ALD       72                       // smem stride in fp16 (144B)
#define AKTILE_B  (64 * ALD * 2)           // 9216 bytes per 64-row tile
#define AQ_B      (64 * ALD * 2)           // Q tile: 9216
#define ASTAGE_B  (2 * AKTILE_B)           // K + V = 18432
#define ATTN_SMEM (AQ_B + 2 * ASTAGE_B + 128)

__global__ void __launch_bounds__(128, 4)
attn_mma_kernel(__half* __restrict__ out)
{
    extern __shared__ char smem[];
    const uint32_t sb     = smem_u32(smem);
    const uint32_t sQ     = sb;
    const uint32_t sStage = sb + AQ_B;

    const int tid  = threadIdx.x;
    const int wid  = tid >> 5;
    const int lane = tid & 31;
    const int qt   = gridDim.x - 1 - blockIdx.x;   // longest first
    const int bh   = blockIdx.y;
    const int q0   = qt * 64;

    const size_t headbase = (size_t)bh * S_ * DEPTH;

    // ---- Load Q tile (64 x 64) ----
    {
        const __half* s = g_q + headbase + (size_t)q0 * DEPTH;
        #pragma unroll
        for (int i = 0; i < 4; i++) {
            const int idx = i * 128 + tid;
            const int row = idx >> 3, ch = idx & 7;
            CP_ASYNC16(sQ + row * (ALD * 2) + ch * 16, s + row * DEPTH + ch * 8);
        }
    }

    auto load_kv = [&](int kt, int buf) {
        const uint32_t st = sStage + buf * ASTAGE_B;
        const size_t base = headbase + (size_t)kt * 64 * DEPTH;
        const __half* kvsrc[2] = {g_k + base, g_v + base};
        #pragma unroll
        for (int t = 0; t < 2; t++) {
            const __half* s = kvsrc[t];
            #pragma unroll
            for (int i = 0; i < 4; i++) {
                const int idx = i * 128 + tid;
                const int row = idx >> 3, ch = idx & 7;
                CP_ASYNC16(st + t * AKTILE_B + row * (ALD * 2) + ch * 16,
                           s + row * DEPTH + ch * 8);
            }
        }
    };

    load_kv(0, 0);
    CP_COMMIT();
    CP_WAIT(0);
    __syncthreads();

    const int a_r = lane & 15;
    const int a_c = (lane >> 4) << 3;
    const int b_r = (lane & 7) + ((lane >> 4) << 3);
    const int b_c = ((lane >> 3) & 1) << 3;
    const int v_r = (lane & 7) + (((lane >> 3) & 1) << 3);
    const int v_c = (lane >> 4) << 3;
    const int er  = lane >> 2;
    const int ec  = (lane & 3) * 2;

    // Q fragments resident in registers (16 regs)
    uint32_t aq[4][4];
    #pragma unroll
    for (int t = 0; t < 4; t++) {
        const int row = wid * 16 + a_r;
        const uint32_t off = row * (ALD * 2) + (t * 16 + a_c) * 2;
        LDSM_X4(aq[t][0], aq[t][1], aq[t][2], aq[t][3], sQ + off);
    }

    // O accumulators (8 n-frags) + per-thread row-sum partials
    float oacc[8][4];
    #pragma unroll
    for (int j = 0; j < 8; j++)
        #pragma unroll
        for (int v = 0; v < 4; v++) oacc[j][v] = 0.0f;
    float ls0 = 0.0f, ls1 = 0.0f;

    for (int kt = 0; kt <= qt; kt++) {
        const int buf = kt & 1;
        if (kt < qt) { load_kv(kt + 1, buf ^ 1); CP_COMMIT(); CP_WAIT(1); }
        else         { CP_WAIT(0); }
        __syncthreads();

        const uint32_t st = sStage + buf * ASTAGE_B;
        const uint32_t tK = st;
        const uint32_t tV = st + AKTILE_B;

        // ---- Scores (exp2-domain logits) ----
        float sacc[8][4];
        #pragma unroll
        for (int j = 0; j < 8; j++)
            #pragma unroll
            for (int v = 0; v < 4; v++) sacc[j][v] = 0.0f;

        #pragma unroll
        for (int t = 0; t < 4; t++) {
            uint32_t kb[8][2];
            #pragma unroll
            for (int g = 0; g < 4; g++) {
                const int row = g * 16 + b_r;
                const uint32_t off = row * (ALD * 2) + (t * 16 + b_c) * 2;
                LDSM_X4(kb[2 * g][0], kb[2 * g][1], kb[2 * g + 1][0], kb[2 * g + 1][1],
                        tK + off);
            }
            #pragma unroll
            for (int nf = 0; nf < 8; nf++)
                MMA_F16(sacc[nf], aq[t], kb[nf]);
        }

        // ---- Causal mask (diagonal tile only) ----
        if (kt == qt) {
            const int colbase = kt * 64;
            const int r0_ = q0 + wid * 16 + er;
            const int r1_ = r0_ + 8;
            #pragma unroll
            for (int nf = 0; nf < 8; nf++) {
                const int c0_ = colbase + nf * 8 + ec;
                if (c0_ > r0_)     sacc[nf][0] = -1e30f;
                if (c0_ + 1 > r0_) sacc[nf][1] = -1e30f;
                if (c0_ > r1_)     sacc[nf][2] = -1e30f;
                if (c0_ + 1 > r1_) sacc[nf][3] = -1e30f;
            }
        }

        // ---- P = exp2(s) via ex2.approx.f16x2; fp32 row-sum partials ----
        uint32_t ph[4][4];
        #pragma unroll
        for (int t = 0; t < 4; t++) {
            #pragma unroll
            for (int k2 = 0; k2 < 2; k2++) {
                const int nf = 2 * t + k2;
                const uint32_t p01 = ex2_h2(pack_h2(sacc[nf][0], sacc[nf][1]));
                const uint32_t p23 = ex2_h2(pack_h2(sacc[nf][2], sacc[nf][3]));
                ph[t][2 * k2 + 0] = p01;
                ph[t][2 * k2 + 1] = p23;
                const float2 f01 = __half22float2(*reinterpret_cast<const __half2*>(&p01));
                const float2 f23 = __half22float2(*reinterpret_cast<const __half2*>(&p23));
                ls0 += f01.x + f01.y;
                ls1 += f23.x + f23.y;
            }
        }

        // ---- O += P @ V (8 n-frags) ----
        #pragma unroll
        for (int t = 0; t < 4; t++) {
            uint32_t vb[8][2];
            #pragma unroll
            for (int g = 0; g < 4; g++) {
                const int row = t * 16 + v_r;
                const uint32_t off = row * (ALD * 2) + (g * 16 + v_c) * 2;
                LDSM_X4_T(vb[2 * g][0], vb[2 * g][1], vb[2 * g + 1][0], vb[2 * g + 1][1],
                          tV + off);
            }
            #pragma unroll
            for (int df = 0; df < 8; df++)
                MMA_F16(oacc[df], ph[t], vb[df]);
        }
        __syncthreads();
    }

    // ---- Quad-reduce row sums, normalize, write out [B,S,D] ----
    ls0 += __shfl_xor_sync(0xffffffffu, ls0, 1);
    ls0 += __shfl_xor_sync(0xffffffffu, ls0, 2);
    ls1 += __shfl_xor_sync(0xffffffffu, ls1, 1);
    ls1 += __shfl_xor_sync(0xffffffffu, ls1, 2);
    const float inv0 = 1.0f / ls0;
    const float inv1 = 1.0f / ls1;

    const int b = bh >> 4;
    const int h = bh & 15;
    const int s0 = q0 + wid * 16 + er;
    #pragma unroll
    for (int df = 0; df < 8; df++) {
        const int col = h * DEPTH + df * 8 + ec;
        *reinterpret_cast<uint32_t*>(&out[((size_t)b * S_ + s0) * D_ + col]) =
            pack_h2(oacc[df][0] * inv0, oacc[df][1] * inv0);
        *reinterpret_cast<uint32_t*>(&out[((size_t)b * S_ + s0 + 8) * D_ + col]) =
            pack_h2(oacc[df][2] * inv1, oacc[df][3] * inv1);
    }
}

// ---------------------------------------------------------------------------
// Launch
// ---------------------------------------------------------------------------
extern "C" void kernel_launch(void* const* d_in, const int* in_sizes, int n_in,
                              void* d_out, int out_size)
{
    (void)in_sizes; (void)n_in; (void)out_size;
    const float* v_in = (const float*)d_in[0];
    const float* k_in = (const float*)d_in[1];
    const float* q_in = (const float*)d_in[2];
    const float* wq = (const float*)d_in[4];
    const float* bq = (const float*)d_in[5];
    const float* wk = (const float*)d_in[6];
    const float* bk = (const float*)d_in[7];
    const float* wv = (const float*)d_in[8];
    const float* bv = (const float*)d_in[9];
    const float* wo = (const float*)d_in[10];
    const float* bo = (const float*)d_in[11];
    float* out = (float*)d_out;

    __half* attn_ptr;
    cudaGetSymbolAddress((void**)&attn_ptr, g_attn);

    static bool attr_set = false;
    if (!attr_set) {
        cudaFuncSetAttribute(attn_mma_kernel,
                             cudaFuncAttributeMaxDynamicSharedMemorySize, ATTN_SMEM);
        cudaFuncSetAttribute(qkv_gemm,
                             cudaFuncAttributeMaxDynamicSharedMemorySize, GEMM_SMEM);
        cudaFuncSetAttribute(out_gemm,
                             cudaFuncAttributeMaxDynamicSharedMemorySize, GEMM_SMEM);
        attr_set = true;
    }

    // 1) Fused prep: input converts (z=0..2) + weight transposes (z=3)
    const int n4 = (int)((size_t)MTOK * D_ / 4);
    const dim3 pgrid(n4 / 256, 1, 4);   // (8192, 1, 4)
    prep_all<<<pgrid, 256>>>(v_in, k_in, q_in, wq, wk, wv, wo);

    // 2) Fused QKV projections (128x128 tiles, 8 warps, 2 CTAs/SM)
    const dim3 qkv_grid(D_ / 128, MTOK / 128, 3);   // (8, 64, 3)
    qkv_gemm<<<qkv_grid, 256, GEMM_SMEM>>>(bq, bk, bv);

    // 3) Causal flash attention (f16x2 exp2 softmax) -> fp16 [B,S,D]
    const dim3 attn_grid(S_ / 64, B_ * H_);   // (32, 64)
    attn_mma_kernel<<<attn_grid, 128, ATTN_SMEM>>>(attn_ptr);

    // 4) Output projection (128x128 tiles, 8 warps, 2 CTAs/SM)
    const dim3 ogrid(D_ / 128, MTOK / 128);   // (8, 64)
    out_gemm<<<ogrid, 256, GEMM_SMEM>>>(bo, out);
}

// round 17
// speedup vs baseline: 1.0700x; 1.0700x over previous
#include <cuda_runtime.h>
#include <cuda_fp16.h>
#include <math.h>
#include <stdint.h>

// Problem constants
#define B_    4
#define S_    2048
#define D_    1024
#define H_    16
#define DEPTH 64
#define MTOK  (B_ * S_)   // 8192 token rows

// ---------------------------------------------------------------------------
// Scratch (device globals; no allocation allowed)
// ---------------------------------------------------------------------------
__device__ __half g_in[3][MTOK * D_];     // fp16 inputs (v,k,q order)
__device__ __half g_wt[4][D_ * D_];       // fp16 transposed weights [N,K]
__device__ __half g_q[MTOK * D_];         // projected, head-split [B,H,S,64]
__device__ __half g_k[MTOK * D_];
__device__ __half g_v[MTOK * D_];
__device__ __half g_attn[MTOK * D_];      // attention output [B,S,D]

// ---------------------------------------------------------------------------
// PTX helpers (sm_103 base target: mma.sync / ldmatrix / cp.async only)
// ---------------------------------------------------------------------------
__device__ __forceinline__ uint32_t smem_u32(const void* p) {
    uint32_t a;
    asm("{ .reg .u64 t; cvta.to.shared.u64 t, %1; cvt.u32.u64 %0, t; }"
        : "=r"(a) : "l"(p));
    return a;
}

#define CP_ASYNC16(dst_u32, src_ptr) \
    asm volatile("cp.async.cg.shared.global [%0], [%1], 16;" \
                 :: "r"(dst_u32), "l"(src_ptr) : "memory")
#define CP_COMMIT() asm volatile("cp.async.commit_group;" ::: "memory")
#define CP_WAIT(n)  asm volatile("cp.async.wait_group %0;" :: "n"(n) : "memory")

#define LDSM_X4(r0, r1, r2, r3, addr) \
    asm volatile("ldmatrix.sync.aligned.m8n8.x4.shared.b16 {%0,%1,%2,%3}, [%4];" \
                 : "=r"(r0), "=r"(r1), "=r"(r2), "=r"(r3) : "r"(addr))

#define LDSM_X4_T(r0, r1, r2, r3, addr) \
    asm volatile("ldmatrix.sync.aligned.m8n8.x4.trans.shared.b16 {%0,%1,%2,%3}, [%4];" \
                 : "=r"(r0), "=r"(r1), "=r"(r2), "=r"(r3) : "r"(addr))

#define MMA_F16(d, a, b) \
    asm volatile("mma.sync.aligned.m16n8k16.row.col.f32.f16.f16.f32 " \
                 "{%0,%1,%2,%3}, {%4,%5,%6,%7}, {%8,%9}, {%0,%1,%2,%3};" \
                 : "+f"((d)[0]), "+f"((d)[1]), "+f"((d)[2]), "+f"((d)[3]) \
                 : "r"((a)[0]), "r"((a)[1]), "r"((a)[2]), "r"((a)[3]), \
                   "r"((b)[0]), "r"((b)[1]))

__device__ __forceinline__ uint32_t pack_h2(float x, float y) {
    __half2 h = __floats2half2_rn(x, y);
    return *reinterpret_cast<uint32_t*>(&h);
}

// element-wise exp2 on a packed half2
__device__ __forceinline__ uint32_t ex2_h2(uint32_t h2) {
    uint32_t r;
    asm("ex2.approx.f16x2 %0, %1;" : "=r"(r) : "r"(h2));
    return r;
}

// ---------------------------------------------------------------------------
// Fused prep kernel: z = 0..2 -> fp32->fp16 input converts (v,k,q);
//                    z = 3    -> all four weight transposes (blocks 0..4095)
// ---------------------------------------------------------------------------
__global__ void __launch_bounds__(256)
prep_all(const float* __restrict__ v, const float* __restrict__ k,
         const float* __restrict__ q,
         const float* __restrict__ wq, const float* __restrict__ wk,
         const float* __restrict__ wv, const float* __restrict__ wo)
{
    const int z = blockIdx.z;
    if (z < 3) {
        const float* src = (z == 0) ? v : (z == 1) ? k : q;
        __half* dst = g_in[z];
        const int i = blockIdx.x * blockDim.x + threadIdx.x;
        float4 val = reinterpret_cast<const float4*>(src)[i];
        uint32_t* dp = reinterpret_cast<uint32_t*>(dst);
        dp[2 * i]     = pack_h2(val.x, val.y);
        dp[2 * i + 1] = pack_h2(val.z, val.w);
    } else {
        if (blockIdx.x >= 4096) return;
        __shared__ float t[32][33];
        const int w = blockIdx.x >> 10;             // weight index 0..3
        const int tile = blockIdx.x & 1023;
        const int nx = (tile & 31) * 32;            // N tile
        const int kx = (tile >> 5) * 32;            // K tile
        const float* W = (w == 0) ? wq : (w == 1) ? wk : (w == 2) ? wv : wo;
        __half* T = g_wt[w];
        const int tx = threadIdx.x & 31;
        const int ty = threadIdx.x >> 5;            // 0..7
        #pragma unroll
        for (int r = 0; r < 32; r += 8)
            t[ty + r][tx] = W[(size_t)(kx + ty + r) * D_ + nx + tx];
        __syncthreads();
        #pragma unroll
        for (int r = 0; r < 32; r += 8)
            T[(size_t)(nx + ty + r) * D_ + kx + tx] = __float2half_rn(t[tx][ty + r]);
    }
}

// ---------------------------------------------------------------------------
// GEMM A (qkv): CTA 128x128, 4 warps (2x2), 64x64 warp tiles, K-block 64,
// 2-stage cp.async, 3 CTAs/SM. Minimal global traffic (A reloads = 8).
// MODE 1 epilogue: fp16 head-split [B,H,S,DEPTH].
// ---------------------------------------------------------------------------
#define LDT        72                        // smem row stride in fp16 (144B)
#define TILE_B     (128 * LDT * 2)           // 18432 bytes (128 rows)
#define STAGE_BA   (2 * TILE_B)              // A + B = 36864
#define GEMM_SMEM_A (2 * STAGE_BA)           // 73728 -> 3 CTAs/SM

__device__ __forceinline__ void
gemm_body_qkv(const __half* __restrict__ A, const __half* __restrict__ Bm,
              const float* __restrict__ bias, __half* __restrict__ Ch, float alpha)
{
    extern __shared__ char smem[];
    const uint32_t sb = smem_u32(smem);

    const int tid  = threadIdx.x;
    const int wid  = tid >> 5;
    const int lane = tid & 31;
    const int wm   = wid & 1;
    const int wn   = wid >> 1;
    const int m0   = blockIdx.y * 128;
    const int n0   = blockIdx.x * 128;

    const __half* srcs[2] = {A, Bm};
    const int rowbase[2] = {m0, n0};

    auto load_stage = [&](int kb, int buf) {
        const uint32_t st = sb + buf * STAGE_BA;
        #pragma unroll
        for (int t = 0; t < 2; t++) {
            const __half* s = srcs[t];
            const int rb = rowbase[t];
            #pragma unroll
            for (int r = 0; r < 8; r++) {
                const int idx  = r * 128 + tid;
                const int row  = idx >> 3;
                const int ch   = idx & 7;
                CP_ASYNC16(st + t * TILE_B + row * (LDT * 2) + ch * 16,
                           s + (size_t)(rb + row) * D_ + kb * 64 + ch * 8);
            }
        }
        CP_COMMIT();
    };

    float acc[4][8][4];
    #pragma unroll
    for (int i = 0; i < 4; i++)
        #pragma unroll
        for (int j = 0; j < 8; j++)
            #pragma unroll
            for (int v = 0; v < 4; v++)
                acc[i][j][v] = 0.0f;

    load_stage(0, 0);
    load_stage(1, 1);

    const int a_r = lane & 15;
    const int a_c = (lane >> 4) << 3;
    const int b_r = (lane & 7) + ((lane >> 4) << 3);
    const int b_c = ((lane >> 3) & 1) << 3;

    const int NITER = D_ / 64;    // 16
    for (int kb = 0; kb < NITER; kb++) {
        if (kb == NITER - 1) { CP_WAIT(0); } else { CP_WAIT(1); }
        __syncthreads();

        const int buf = kb & 1;
        const uint32_t st = sb + buf * STAGE_BA;
        const uint32_t tA = st;
        const uint32_t tB = st + TILE_B;

        #pragma unroll
        for (int ks = 0; ks < 64; ks += 16) {
            uint32_t ah[4][4];
            #pragma unroll
            for (int mf = 0; mf < 4; mf++) {
                const int row = wm * 64 + mf * 16 + a_r;
                const uint32_t off = row * (LDT * 2) + (ks + a_c) * 2;
                LDSM_X4(ah[mf][0], ah[mf][1], ah[mf][2], ah[mf][3], tA + off);
            }
            uint32_t bh[8][2];
            #pragma unroll
            for (int gp = 0; gp < 4; gp++) {
                const int row = wn * 64 + gp * 16 + b_r;
                const uint32_t off = row * (LDT * 2) + (ks + b_c) * 2;
                LDSM_X4(bh[2 * gp][0], bh[2 * gp][1], bh[2 * gp + 1][0], bh[2 * gp + 1][1],
                        tB + off);
            }
            #pragma unroll
            for (int mf = 0; mf < 4; mf++)
                #pragma unroll
                for (int nf = 0; nf < 8; nf++)
                    MMA_F16(acc[mf][nf], ah[mf], bh[nf]);
        }
        __syncthreads();
        if (kb + 2 < NITER) load_stage(kb + 2, buf);
    }

    const int er = lane >> 2;
    const int ec = (lane & 3) * 2;
    #pragma unroll
    for (int mf = 0; mf < 4; mf++) {
        #pragma unroll
        for (int nf = 0; nf < 8; nf++) {
            const int n  = n0 + wn * 64 + nf * 8 + ec;
            const float b0 = bias[n], b1 = bias[n + 1];
            #pragma unroll
            for (int half = 0; half < 2; half++) {
                const int m = m0 + wm * 64 + mf * 16 + er + half * 8;
                const float vx = (acc[mf][nf][half * 2 + 0] + b0) * alpha;
                const float vy = (acc[mf][nf][half * 2 + 1] + b1) * alpha;
                const int b  = m >> 11;
                const int s  = m & 2047;
                const int h  = n >> 6;
                const int dd = n & 63;
                const size_t idx = (((size_t)(b * H_ + h)) * S_ + s) * DEPTH + dd;
                *reinterpret_cast<uint32_t*>(&Ch[idx]) = pack_h2(vx, vy);
            }
        }
    }
}

// Q pre-scaled by (1/8)*log2(e) so softmax runs in exp2 domain.
#define QSCALE_LOG2E 0.1803368801111244f

__global__ void __launch_bounds__(128, 3)
qkv_gemm(const float* __restrict__ bq, const float* __restrict__ bk,
         const float* __restrict__ bv)
{
    const int z = blockIdx.z;
    if (z == 0) {
        gemm_body_qkv(g_in[2], g_wt[0], bq, g_q, QSCALE_LOG2E);
    } else if (z == 1) {
        gemm_body_qkv(g_in[1], g_wt[1], bk, g_k, 1.0f);
    } else {
        gemm_body_qkv(g_in[0], g_wt[2], bv, g_v, 1.0f);
    }
}

// ---------------------------------------------------------------------------
// GEMM B (out): CTA 128(M) x 64(N), 4 warps (2x2), 64x32 warp tiles, K-block
// 64, 2-stage, 4 CTAs/SM. Tail-dominated single GEMM: 1024 CTAs -> 86% wave
// utilization. Epilogue: fp32 row-major [M,N].
// ---------------------------------------------------------------------------
#define ATILE_G     (128 * LDT * 2)          // 18432
#define BTILE_G     (64 * LDT * 2)           // 9216
#define STAGE_BB    (ATILE_G + BTILE_G)      // 27648
#define GEMM_SMEM_B (2 * STAGE_BB)           // 55296 -> 4 CTAs/SM

__global__ void __launch_bounds__(128, 4)
out_gemm(const float* __restrict__ bias, float* __restrict__ C)
{
    extern __shared__ char smem[];
    const uint32_t sb = smem_u32(smem);

    const __half* A  = g_attn;
    const __half* Bm = g_wt[3];

    const int tid  = threadIdx.x;
    const int wid  = tid >> 5;
    const int lane = tid & 31;
    const int wm   = wid & 1;            // warp row -> 64 M-rows
    const int wn   = wid >> 1;           // warp col -> 32 N-cols
    const int m0   = blockIdx.y * 128;
    const int n0   = blockIdx.x * 64;

    auto load_stage = [&](int kb, int buf) {
        const uint32_t st = sb + buf * STAGE_BB;
        #pragma unroll
        for (int r = 0; r < 8; r++) {
            const int idx = r * 128 + tid;
            const int row = idx >> 3;
            const int ch  = idx & 7;
            CP_ASYNC16(st + row * (LDT * 2) + ch * 16,
                       A + (size_t)(m0 + row) * D_ + kb * 64 + ch * 8);
        }
        #pragma unroll
        for (int r = 0; r < 4; r++) {
            const int idx = r * 128 + tid;
            const int row = idx >> 3;
            const int ch  = idx & 7;
            CP_ASYNC16(st + ATILE_G + row * (LDT * 2) + ch * 16,
                       Bm + (size_t)(n0 + row) * D_ + kb * 64 + ch * 8);
        }
        CP_COMMIT();
    };

    float acc[4][4][4];
    #pragma unroll
    for (int i = 0; i < 4; i++)
        #pragma unroll
        for (int j = 0; j < 4; j++)
            #pragma unroll
            for (int v = 0; v < 4; v++)
                acc[i][j][v] = 0.0f;

    load_stage(0, 0);
    load_stage(1, 1);

    const int a_r = lane & 15;
    const int a_c = (lane >> 4) << 3;
    const int b_r = (lane & 7) + ((lane >> 4) << 3);
    const int b_c = ((lane >> 3) & 1) << 3;

    const int NITER = D_ / 64;    // 16
    for (int kb = 0; kb < NITER; kb++) {
        if (kb == NITER - 1) { CP_WAIT(0); } else { CP_WAIT(1); }
        __syncthreads();

        const int buf = kb & 1;
        const uint32_t st = sb + buf * STAGE_BB;
        const uint32_t tA = st;
        const uint32_t tB = st + ATILE_G;

        #pragma unroll
        for (int ks = 0; ks < 64; ks += 16) {
            uint32_t ah[4][4];
            #pragma unroll
            for (int mf = 0; mf < 4; mf++) {
                const int row = wm * 64 + mf * 16 + a_r;
                const uint32_t off = row * (LDT * 2) + (ks + a_c) * 2;
                LDSM_X4(ah[mf][0], ah[mf][1], ah[mf][2], ah[mf][3], tA + off);
            }
            uint32_t bh[4][2];
            #pragma unroll
            for (int gp = 0; gp < 2; gp++) {
                const int row = wn * 32 + gp * 16 + b_r;
                const uint32_t off = row * (LDT * 2) + (ks + b_c) * 2;
                LDSM_X4(bh[2 * gp][0], bh[2 * gp][1], bh[2 * gp + 1][0], bh[2 * gp + 1][1],
                        tB + off);
            }
            #pragma unroll
            for (int mf = 0; mf < 4; mf++)
                #pragma unroll
                for (int nf = 0; nf < 4; nf++)
                    MMA_F16(acc[mf][nf], ah[mf], bh[nf]);
        }
        __syncthreads();
        if (kb + 2 < NITER) load_stage(kb + 2, buf);
    }

    const int er = lane >> 2;
    const int ec = (lane & 3) * 2;
    #pragma unroll
    for (int mf = 0; mf < 4; mf++) {
        #pragma unroll
        for (int nf = 0; nf < 4; nf++) {
            const int n  = n0 + wn * 32 + nf * 8 + ec;
            const float b0 = bias[n], b1 = bias[n + 1];
            #pragma unroll
            for (int half = 0; half < 2; half++) {
                const int m = m0 + wm * 64 + mf * 16 + er + half * 8;
                float2 v;
                v.x = acc[mf][nf][half * 2 + 0] + b0;
                v.y = acc[mf][nf][half * 2 + 1] + b1;
                *reinterpret_cast<float2*>(&C[(size_t)m * D_ + n]) = v;
            }
        }
    }
}

// ---------------------------------------------------------------------------
// Flash attention, fixed-scale exp2 softmax (no online max; bounded logits).
// exp via ex2.approx.f16x2; fp32 row-sum partials, quad-reduced at the end.
// CTA q-tile 64 rows, 4 warps x 16 q-rows, 4 CTAs/SM. K/V double buffered.
// Grid: (S/64, B*H), qt reversed (longest first).
// ---------------------------------------------------------------------------
#define ALD       72                       // smem stride in fp16 (144B)
#define AKTILE_B  (64 * ALD * 2)           // 9216 bytes per 64-row tile
#define AQ_B      (64 * ALD * 2)           // Q tile: 9216
#define ASTAGE_B  (2 * AKTILE_B)           // K + V = 18432
#define ATTN_SMEM (AQ_B + 2 * ASTAGE_B + 128)

__global__ void __launch_bounds__(128, 4)
attn_mma_kernel(__half* __restrict__ out)
{
    extern __shared__ char smem[];
    const uint32_t sb     = smem_u32(smem);
    const uint32_t sQ     = sb;
    const uint32_t sStage = sb + AQ_B;

    const int tid  = threadIdx.x;
    const int wid  = tid >> 5;
    const int lane = tid & 31;
    const int qt   = gridDim.x - 1 - blockIdx.x;   // longest first
    const int bh   = blockIdx.y;
    const int q0   = qt * 64;

    const size_t headbase = (size_t)bh * S_ * DEPTH;

    // ---- Load Q tile (64 x 64) ----
    {
        const __half* s = g_q + headbase + (size_t)q0 * DEPTH;
        #pragma unroll
        for (int i = 0; i < 4; i++) {
            const int idx = i * 128 + tid;
            const int row = idx >> 3, ch = idx & 7;
            CP_ASYNC16(sQ + row * (ALD * 2) + ch * 16, s + row * DEPTH + ch * 8);
        }
    }

    auto load_kv = [&](int kt, int buf) {
        const uint32_t st = sStage + buf * ASTAGE_B;
        const size_t base = headbase + (size_t)kt * 64 * DEPTH;
        const __half* kvsrc[2] = {g_k + base, g_v + base};
        #pragma unroll
        for (int t = 0; t < 2; t++) {
            const __half* s = kvsrc[t];
            #pragma unroll
            for (int i = 0; i < 4; i++) {
                const int idx = i * 128 + tid;
                const int row = idx >> 3, ch = idx & 7;
                CP_ASYNC16(st + t * AKTILE_B + row * (ALD * 2) + ch * 16,
                           s + row * DEPTH + ch * 8);
            }
        }
    };

    load_kv(0, 0);
    CP_COMMIT();
    CP_WAIT(0);
    __syncthreads();

    const int a_r = lane & 15;
    const int a_c = (lane >> 4) << 3;
    const int b_r = (lane & 7) + ((lane >> 4) << 3);
    const int b_c = ((lane >> 3) & 1) << 3;
    const int v_r = (lane & 7) + (((lane >> 3) & 1) << 3);
    const int v_c = (lane >> 4) << 3;
    const int er  = lane >> 2;
    const int ec  = (lane & 3) * 2;

    // Q fragments resident in registers (16 regs)
    uint32_t aq[4][4];
    #pragma unroll
    for (int t = 0; t < 4; t++) {
        const int row = wid * 16 + a_r;
        const uint32_t off = row * (ALD * 2) + (t * 16 + a_c) * 2;
        LDSM_X4(aq[t][0], aq[t][1], aq[t][2], aq[t][3], sQ + off);
    }

    // O accumulators (8 n-frags) + per-thread row-sum partials
    float oacc[8][4];
    #pragma unroll
    for (int j = 0; j < 8; j++)
        #pragma unroll
        for (int v = 0; v < 4; v++) oacc[j][v] = 0.0f;
    float ls0 = 0.0f, ls1 = 0.0f;

    for (int kt = 0; kt <= qt; kt++) {
        const int buf = kt & 1;
        if (kt < qt) { load_kv(kt + 1, buf ^ 1); CP_COMMIT(); CP_WAIT(1); }
        else         { CP_WAIT(0); }
        __syncthreads();

        const uint32_t st = sStage + buf * ASTAGE_B;
        const uint32_t tK = st;
        const uint32_t tV = st + AKTILE_B;

        // ---- Scores (exp2-domain logits) ----
        float sacc[8][4];
        #pragma unroll
        for (int j = 0; j < 8; j++)
            #pragma unroll
            for (int v = 0; v < 4; v++) sacc[j][v] = 0.0f;

        #pragma unroll
        for (int t = 0; t < 4; t++) {
            uint32_t kb[8][2];
            #pragma unroll
            for (int g = 0; g < 4; g++) {
                const int row = g * 16 + b_r;
                const uint32_t off = row * (ALD * 2) + (t * 16 + b_c) * 2;
                LDSM_X4(kb[2 * g][0], kb[2 * g][1], kb[2 * g + 1][0], kb[2 * g + 1][1],
                        tK + off);
            }
            #pragma unroll
            for (int nf = 0; nf < 8; nf++)
                MMA_F16(sacc[nf], aq[t], kb[nf]);
        }

        // ---- Causal mask (diagonal tile only) ----
        if (kt == qt) {
            const int colbase = kt * 64;
            const int r0_ = q0 + wid * 16 + er;
            const int r1_ = r0_ + 8;
            #pragma unroll
            for (int nf = 0; nf < 8; nf++) {
                const int c0_ = colbase + nf * 8 + ec;
                if (c0_ > r0_)     sacc[nf][0] = -1e30f;
                if (c0_ + 1 > r0_) sacc[nf][1] = -1e30f;
                if (c0_ > r1_)     sacc[nf][2] = -1e30f;
                if (c0_ + 1 > r1_) sacc[nf][3] = -1e30f;
            }
        }

        // ---- P = exp2(s) via ex2.approx.f16x2; fp32 row-sum partials ----
        uint32_t ph[4][4];
        #pragma unroll
        for (int t = 0; t < 4; t++) {
            #pragma unroll
            for (int k2 = 0; k2 < 2; k2++) {
                const int nf = 2 * t + k2;
                const uint32_t p01 = ex2_h2(pack_h2(sacc[nf][0], sacc[nf][1]));
                const uint32_t p23 = ex2_h2(pack_h2(sacc[nf][2], sacc[nf][3]));
                ph[t][2 * k2 + 0] = p01;
                ph[t][2 * k2 + 1] = p23;
                const float2 f01 = __half22float2(*reinterpret_cast<const __half2*>(&p01));
                const float2 f23 = __half22float2(*reinterpret_cast<const __half2*>(&p23));
                ls0 += f01.x + f01.y;
                ls1 += f23.x + f23.y;
            }
        }

        // ---- O += P @ V (8 n-frags) ----
        #pragma unroll
        for (int t = 0; t < 4; t++) {
            uint32_t vb[8][2];
            #pragma unroll
            for (int g = 0; g < 4; g++) {
                const int row = t * 16 + v_r;
                const uint32_t off = row * (ALD * 2) + (g * 16 + v_c) * 2;
                LDSM_X4_T(vb[2 * g][0], vb[2 * g][1], vb[2 * g + 1][0], vb[2 * g + 1][1],
                          tV + off);
            }
            #pragma unroll
            for (int df = 0; df < 8; df++)
                MMA_F16(oacc[df], ph[t], vb[df]);
        }
        __syncthreads();
    }

    // ---- Quad-reduce row sums, normalize, write out [B,S,D] ----
    ls0 += __shfl_xor_sync(0xffffffffu, ls0, 1);
    ls0 += __shfl_xor_sync(0xffffffffu, ls0, 2);
    ls1 += __shfl_xor_sync(0xffffffffu, ls1, 1);
    ls1 += __shfl_xor_sync(0xffffffffu, ls1, 2);
    const float inv0 = 1.0f / ls0;
    const float inv1 = 1.0f / ls1;

    const int b = bh >> 4;
    const int h = bh & 15;
    const int s0 = q0 + wid * 16 + er;
    #pragma unroll
    for (int df = 0; df < 8; df++) {
        const int col = h * DEPTH + df * 8 + ec;
        *reinterpret_cast<uint32_t*>(&out[((size_t)b * S_ + s0) * D_ + col]) =
            pack_h2(oacc[df][0] * inv0, oacc[df][1] * inv0);
        *reinterpret_cast<uint32_t*>(&out[((size_t)b * S_ + s0 + 8) * D_ + col]) =
            pack_h2(oacc[df][2] * inv1, oacc[df][3] * inv1);
    }
}

// ---------------------------------------------------------------------------
// Launch
// ---------------------------------------------------------------------------
extern "C" void kernel_launch(void* const* d_in, const int* in_sizes, int n_in,
                              void* d_out, int out_size)
{
    (void)in_sizes; (void)n_in; (void)out_size;
    const float* v_in = (const float*)d_in[0];
    const float* k_in = (const float*)d_in[1];
    const float* q_in = (const float*)d_in[2];
    const float* wq = (const float*)d_in[4];
    const float* bq = (const float*)d_in[5];
    const float* wk = (const float*)d_in[6];
    const float* bk = (const float*)d_in[7];
    const float* wv = (const float*)d_in[8];
    const float* bv = (const float*)d_in[9];
    const float* wo = (const float*)d_in[10];
    const float* bo = (const float*)d_in[11];
    float* out = (float*)d_out;

    __half* attn_ptr;
    cudaGetSymbolAddress((void**)&attn_ptr, g_attn);

    static bool attr_set = false;
    if (!attr_set) {
        cudaFuncSetAttribute(attn_mma_kernel,
                             cudaFuncAttributeMaxDynamicSharedMemorySize, ATTN_SMEM);
        cudaFuncSetAttribute(qkv_gemm,
                             cudaFuncAttributeMaxDynamicSharedMemorySize, GEMM_SMEM_A);
        cudaFuncSetAttribute(out_gemm,
                             cudaFuncAttributeMaxDynamicSharedMemorySize, GEMM_SMEM_B);
        attr_set = true;
    }

    // 1) Fused prep: input converts (z=0..2) + weight transposes (z=3)
    const int n4 = (int)((size_t)MTOK * D_ / 4);
    const dim3 pgrid(n4 / 256, 1, 4);   // (8192, 1, 4)
    prep_all<<<pgrid, 256>>>(v_in, k_in, q_in, wq, wk, wv, wo);

    // 2) Fused QKV projections (128x128 tiles, low traffic)
    const dim3 qkv_grid(D_ / 128, MTOK / 128, 3);   // (8, 64, 3)
    qkv_gemm<<<qkv_grid, 128, GEMM_SMEM_A>>>(bq, bk, bv);

    // 3) Causal flash attention (f16x2 exp2 softmax) -> fp16 [B,S,D]
    const dim3 attn_grid(S_ / 64, B_ * H_);   // (32, 64)
    attn_mma_kernel<<<attn_grid, 128, ATTN_SMEM>>>(attn_ptr);

    // 4) Output projection (128x64 tiles, better tail utilization)
    const dim3 ogrid(D_ / 64, MTOK / 128);    // (16, 64)
    out_gemm<<<ogrid, 128, GEMM_SMEM_B>>>(bo, out);
}